// round 5
// baseline (speedup 1.0000x reference)
#include <cuda_runtime.h>

#define Lq 128
#define Bq 128
#define Dq 1024
#define Aq 1024
#define Hq 2048
#define KSPLIT 8
#define KC (Dq / KSPLIT)   // 128 k per split block

typedef unsigned long long ull;

// Scratch (device globals: allocation-free, graph-safe)
__device__ float g_projp[KSPLIT * Bq * Aq];  // split-K partials
__device__ float g_proj[Bq * Aq];            // reduced proj + bias
__device__ float g_scores[Bq * Lq];          // (B, L) transposed
__device__ float g_eT[Bq * Lq];              // normalized e, (B, L)

__device__ __forceinline__ float tanh_fast(float x) {
    float y;
    asm("tanh.approx.f32 %0, %1;" : "=f"(y) : "f"(x));
    return y;
}
__device__ __forceinline__ ull pack2(float x, float y) {
    ull r;
    asm("mov.b64 %0, {%1, %2};" : "=l"(r) : "f"(x), "f"(y));
    return r;
}
__device__ __forceinline__ void unpack2(ull v, float& lo, float& hi) {
    asm("mov.b64 {%0, %1}, %2;" : "=f"(lo), "=f"(hi) : "l"(v));
}
__device__ __forceinline__ ull ffma2(ull a, ull b, ull c) {
    ull d;
    asm("fma.rn.f32x2 %0, %1, %2, %3;" : "=l"(d) : "l"(a), "l"(b), "l"(c));
    return d;
}

// ---------------------------------------------------------------------------
// K1: proj partials. Register-tiled SGEMM: 128(b) x 64(a) tile, KT=16,
// split-K=8. 256 threads; 8(m) x 4(n) register tile per thread as f32x2.
// Grid: (A/64, KSPLIT) = (16, 8) = 128 blocks (one wave).
// ---------------------------------------------------------------------------
__global__ void __launch_bounds__(256) k_proj(const float* __restrict__ S,
                                              const float* __restrict__ W) {
    const int a0    = blockIdx.x * 64;
    const int kbase = blockIdx.y * KC;

    __shared__ float As[16][132];  // [k][m]
    __shared__ float Bs[16][68];   // [k][n]

    const int t  = threadIdx.x;
    const int ar = t >> 1;
    const int ac = (t & 1) * 8;
    const int br = t >> 2;
    const int bc = (t & 3) * 4;
    const int tx = t & 15;
    const int ty = t >> 4;

    ull acc[4][4];
#pragma unroll
    for (int i = 0; i < 4; ++i)
#pragma unroll
        for (int j = 0; j < 4; ++j) acc[i][j] = 0ull;

    for (int kt = 0; kt < KC; kt += 16) {
        const int k0 = kbase + kt;
        float4 av0 = *(const float4*)(S + (size_t)ar * Dq + k0 + ac);
        float4 av1 = *(const float4*)(S + (size_t)ar * Dq + k0 + ac + 4);
        float4 bv  = *(const float4*)(W + (size_t)(a0 + br) * Dq + k0 + bc);
        __syncthreads();
        As[ac + 0][ar] = av0.x;  As[ac + 1][ar] = av0.y;
        As[ac + 2][ar] = av0.z;  As[ac + 3][ar] = av0.w;
        As[ac + 4][ar] = av1.x;  As[ac + 5][ar] = av1.y;
        As[ac + 6][ar] = av1.z;  As[ac + 7][ar] = av1.w;
        Bs[bc + 0][br] = bv.x;   Bs[bc + 1][br] = bv.y;
        Bs[bc + 2][br] = bv.z;   Bs[bc + 3][br] = bv.w;
        __syncthreads();
#pragma unroll
        for (int kk = 0; kk < 16; ++kk) {
            ulonglong2 a01 = *(const ulonglong2*)&As[kk][ty * 8];
            ulonglong2 a23 = *(const ulonglong2*)&As[kk][ty * 8 + 4];
            float4 b = *(const float4*)&Bs[kk][tx * 4];
            ull b0 = pack2(b.x, b.x), b1 = pack2(b.y, b.y);
            ull b2 = pack2(b.z, b.z), b3 = pack2(b.w, b.w);
            acc[0][0] = ffma2(a01.x, b0, acc[0][0]);
            acc[0][1] = ffma2(a01.x, b1, acc[0][1]);
            acc[0][2] = ffma2(a01.x, b2, acc[0][2]);
            acc[0][3] = ffma2(a01.x, b3, acc[0][3]);
            acc[1][0] = ffma2(a01.y, b0, acc[1][0]);
            acc[1][1] = ffma2(a01.y, b1, acc[1][1]);
            acc[1][2] = ffma2(a01.y, b2, acc[1][2]);
            acc[1][3] = ffma2(a01.y, b3, acc[1][3]);
            acc[2][0] = ffma2(a23.x, b0, acc[2][0]);
            acc[2][1] = ffma2(a23.x, b1, acc[2][1]);
            acc[2][2] = ffma2(a23.x, b2, acc[2][2]);
            acc[2][3] = ffma2(a23.x, b3, acc[2][3]);
            acc[3][0] = ffma2(a23.y, b0, acc[3][0]);
            acc[3][1] = ffma2(a23.y, b1, acc[3][1]);
            acc[3][2] = ffma2(a23.y, b2, acc[3][2]);
            acc[3][3] = ffma2(a23.y, b3, acc[3][3]);
        }
    }

    float* base = g_projp + (size_t)blockIdx.y * Bq * Aq + a0 + tx * 4;
#pragma unroll
    for (int mi = 0; mi < 4; ++mi) {
        float4 r0, r1;
        unpack2(acc[mi][0], r0.x, r1.x);
        unpack2(acc[mi][1], r0.y, r1.y);
        unpack2(acc[mi][2], r0.z, r1.z);
        unpack2(acc[mi][3], r0.w, r1.w);
        const int m = ty * 8 + 2 * mi;
        *(float4*)(base + (size_t)m * Aq)       = r0;
        *(float4*)(base + (size_t)(m + 1) * Aq) = r1;
    }
}

// ---------------------------------------------------------------------------
// K2: g_proj = sum_z partials + bias.  Grid 128 x 256 thr, float4/thread.
// ---------------------------------------------------------------------------
__global__ void __launch_bounds__(256) k_reduce(const float* __restrict__ bsa) {
    const int idx = (blockIdx.x * 256 + threadIdx.x) * 4;
    const int a   = idx & (Aq - 1);
    float4 s = *(const float4*)(bsa + a);
#pragma unroll
    for (int z = 0; z < KSPLIT; ++z) {
        float4 p = *(const float4*)(g_projp + (size_t)z * Bq * Aq + idx);
        s.x += p.x;  s.y += p.y;  s.z += p.z;  s.w += p.w;
    }
    *(float4*)(g_proj + idx) = s;
}

// ---------------------------------------------------------------------------
// K3: score[b,l] = sum_a w_a1[a] * tanh(proj[b,a] + uh[l,b,a])
// One warp per (l,b); 8 warps share one b. uh streamed with evict-first.
// Grid: B * L/8 = 2048 blocks, 256 threads. Writes scores transposed (B,L).
// ---------------------------------------------------------------------------
__global__ void __launch_bounds__(256) k_scores(const float* __restrict__ uh,
                                                const float* __restrict__ w1) {
    const int b  = blockIdx.x >> 4;
    const int l0 = (blockIdx.x & 15) << 3;
    __shared__ float ps[Aq];
    __shared__ float ws[Aq];
    const int t  = threadIdx.x;
    const int i4 = t * 4;

    *(float4*)&ps[i4] = *(const float4*)(g_proj + (size_t)b * Aq + i4);
    *(float4*)&ws[i4] = *(const float4*)(w1 + i4);
    __syncthreads();

    const int w    = t >> 5;
    const int lane = t & 31;
    const int l    = l0 + w;
    const float* u = uh + (size_t)(l * Bq + b) * Aq;

    float acc = 0.f;
#pragma unroll
    for (int i = 0; i < 8; ++i) {
        int idx = i * 128 + lane * 4;
        float4 u4 = __ldcs((const float4*)(u + idx));
        float4 p4 = *(const float4*)&ps[idx];
        float4 w4 = *(const float4*)&ws[idx];
        acc = fmaf(w4.x, tanh_fast(p4.x + u4.x), acc);
        acc = fmaf(w4.y, tanh_fast(p4.y + u4.y), acc);
        acc = fmaf(w4.z, tanh_fast(p4.z + u4.z), acc);
        acc = fmaf(w4.w, tanh_fast(p4.w + u4.w), acc);
    }
#pragma unroll
    for (int off = 16; off; off >>= 1)
        acc += __shfl_xor_sync(0xffffffffu, acc, off);
    if (lane == 0) g_scores[b * Lq + l] = acc;   // transposed
}

// ---------------------------------------------------------------------------
// K4: softmax over L. Block per b (128 blocks), 128 threads (one per l).
// Writes e_ij in required (L,B) layout AND transposed (B,L) for k_attend.
// ---------------------------------------------------------------------------
__global__ void __launch_bounds__(128) k_softmax(const float* __restrict__ mask,
                                                 const float* __restrict__ ba1,
                                                 float* __restrict__ e_out) {
    const int b = blockIdx.x;
    const int l = threadIdx.x;
    float e = __expf(g_scores[b * Lq + l] + ba1[0]) * mask[l * Bq + b];

    float v = e;
#pragma unroll
    for (int off = 16; off; off >>= 1)
        v += __shfl_xor_sync(0xffffffffu, v, off);
    __shared__ float part[4];
    if ((l & 31) == 0) part[l >> 5] = v;
    __syncthreads();
    float s = part[0] + part[1] + part[2] + part[3];
    float r = e / s;
    e_out[l * Bq + b] = r;
    g_eT[b * Lq + l]  = r;
}

// ---------------------------------------------------------------------------
// K5: attend[b,h] = sum_l e[l,b] * xs_h[l,b,h]
// Block = (b, 256-wide h chunk), 256 threads = 64 cols(x4) * 4 l-groups.
// Minimal prologue (coalesced e load), dual acc chains, evict-first stream.
// Grid: B*8 = 1024 blocks.
// ---------------------------------------------------------------------------
__global__ void __launch_bounds__(256) k_attend(const float* __restrict__ xs,
                                                float* __restrict__ out) {
    const int b  = blockIdx.x >> 3;
    const int h0 = (blockIdx.x & 7) * 256;
    const int t  = threadIdx.x;

    __shared__ float  es[Lq];
    __shared__ float4 pacc[256];

    if (t < 128) es[t] = g_eT[b * Lq + t];
    __syncthreads();

    const int col = t & 63;
    const int g   = t >> 6;
    const float* base = xs + (size_t)(g * 32) * Bq * Hq +
                        (size_t)b * Hq + h0 + col * 4;
    float4 acc0 = make_float4(0.f, 0.f, 0.f, 0.f);
    float4 acc1 = make_float4(0.f, 0.f, 0.f, 0.f);
#pragma unroll
    for (int i = 0; i < 32; i += 2) {
        float4 v0 = __ldcs((const float4*)(base + (size_t)i * Bq * Hq));
        float4 v1 = __ldcs((const float4*)(base + (size_t)(i + 1) * Bq * Hq));
        float e0 = es[g * 32 + i];
        float e1 = es[g * 32 + i + 1];
        acc0.x = fmaf(e0, v0.x, acc0.x);
        acc0.y = fmaf(e0, v0.y, acc0.y);
        acc0.z = fmaf(e0, v0.z, acc0.z);
        acc0.w = fmaf(e0, v0.w, acc0.w);
        acc1.x = fmaf(e1, v1.x, acc1.x);
        acc1.y = fmaf(e1, v1.y, acc1.y);
        acc1.z = fmaf(e1, v1.z, acc1.z);
        acc1.w = fmaf(e1, v1.w, acc1.w);
    }
    acc0.x += acc1.x;  acc0.y += acc1.y;
    acc0.z += acc1.z;  acc0.w += acc1.w;
    pacc[t] = acc0;
    __syncthreads();
    if (g == 0) {
        float4 p1 = pacc[col + 64];
        float4 p2 = pacc[col + 128];
        float4 p3 = pacc[col + 192];
        acc0.x += (p1.x + p2.x) + p3.x;
        acc0.y += (p1.y + p2.y) + p3.y;
        acc0.z += (p1.z + p2.z) + p3.z;
        acc0.w += (p1.w + p2.w) + p3.w;
        *(float4*)(out + (size_t)b * Hq + h0 + col * 4) = acc0;
    }
}

// ---------------------------------------------------------------------------
extern "C" void kernel_launch(void* const* d_in, const int* in_sizes, int n_in,
                              void* d_out, int out_size) {
    const float* s_tm1 = (const float*)d_in[0];
    const float* xs_h  = (const float*)d_in[1];
    const float* uh    = (const float*)d_in[2];
    const float* mask  = (const float*)d_in[3];
    const float* W_sa  = (const float*)d_in[4];
    const float* b_sa  = (const float*)d_in[5];
    const float* w_a1  = (const float*)d_in[6];
    const float* b_a1  = (const float*)d_in[7];
    float* out = (float*)d_out;  // [0 : L*B) = e_ij, [L*B : ) = attend

    k_proj<<<dim3(16, KSPLIT), 256>>>(s_tm1, W_sa);
    k_reduce<<<128, 256>>>(b_sa);
    k_scores<<<2048, 256>>>(uh, w_a1);
    k_softmax<<<128, 128>>>(mask, b_a1, out);
    k_attend<<<1024, 256>>>(xs_h, out + Lq * Bq);
}

// round 6
// speedup vs baseline: 1.0339x; 1.0339x over previous
#include <cuda_runtime.h>

#define Lq 128
#define Bq 128
#define Dq 1024
#define Aq 1024
#define Hq 2048
#define KSPLIT 8
#define KC (Dq / KSPLIT)

typedef unsigned long long ull;

// Scratch (device globals: allocation-free, graph-safe)
__device__ float g_projp[KSPLIT * Bq * Aq];  // split-K partials
__device__ float g_proj[Bq * Aq];            // reduced proj + bias
__device__ float g_eT[Bq * Lq];              // UNNORMALIZED e~ = exp(score+b)*mask, (B,L)

__device__ __forceinline__ float tanh_fast(float x) {
    float y;
    asm("tanh.approx.f32 %0, %1;" : "=f"(y) : "f"(x));
    return y;
}
__device__ __forceinline__ ull pack2(float x, float y) {
    ull r;
    asm("mov.b64 %0, {%1, %2};" : "=l"(r) : "f"(x), "f"(y));
    return r;
}
__device__ __forceinline__ void unpack2(ull v, float& lo, float& hi) {
    asm("mov.b64 {%0, %1}, %2;" : "=f"(lo), "=f"(hi) : "l"(v));
}
__device__ __forceinline__ ull ffma2(ull a, ull b, ull c) {
    ull d;
    asm("fma.rn.f32x2 %0, %1, %2, %3;" : "=l"(d) : "l"(a), "l"(b), "l"(c));
    return d;
}

// ---------------------------------------------------------------------------
// K1: proj partials. Register-tiled f32x2 SGEMM: 128(b) x 64(a), KT=16,
// split-K=8. Grid (16, 8) = 128 blocks (one wave), 256 threads.
// ---------------------------------------------------------------------------
__global__ void __launch_bounds__(256) k_proj(const float* __restrict__ S,
                                              const float* __restrict__ W) {
    const int a0    = blockIdx.x * 64;
    const int kbase = blockIdx.y * KC;

    __shared__ float As[16][132];  // [k][m]
    __shared__ float Bs[16][68];   // [k][n]

    const int t  = threadIdx.x;
    const int ar = t >> 1;
    const int ac = (t & 1) * 8;
    const int br = t >> 2;
    const int bc = (t & 3) * 4;
    const int tx = t & 15;
    const int ty = t >> 4;

    ull acc[4][4];
#pragma unroll
    for (int i = 0; i < 4; ++i)
#pragma unroll
        for (int j = 0; j < 4; ++j) acc[i][j] = 0ull;

    for (int kt = 0; kt < KC; kt += 16) {
        const int k0 = kbase + kt;
        float4 av0 = *(const float4*)(S + (size_t)ar * Dq + k0 + ac);
        float4 av1 = *(const float4*)(S + (size_t)ar * Dq + k0 + ac + 4);
        float4 bv  = *(const float4*)(W + (size_t)(a0 + br) * Dq + k0 + bc);
        __syncthreads();
        As[ac + 0][ar] = av0.x;  As[ac + 1][ar] = av0.y;
        As[ac + 2][ar] = av0.z;  As[ac + 3][ar] = av0.w;
        As[ac + 4][ar] = av1.x;  As[ac + 5][ar] = av1.y;
        As[ac + 6][ar] = av1.z;  As[ac + 7][ar] = av1.w;
        Bs[bc + 0][br] = bv.x;   Bs[bc + 1][br] = bv.y;
        Bs[bc + 2][br] = bv.z;   Bs[bc + 3][br] = bv.w;
        __syncthreads();
#pragma unroll
        for (int kk = 0; kk < 16; ++kk) {
            ulonglong2 a01 = *(const ulonglong2*)&As[kk][ty * 8];
            ulonglong2 a23 = *(const ulonglong2*)&As[kk][ty * 8 + 4];
            float4 b = *(const float4*)&Bs[kk][tx * 4];
            ull b0 = pack2(b.x, b.x), b1 = pack2(b.y, b.y);
            ull b2 = pack2(b.z, b.z), b3 = pack2(b.w, b.w);
            acc[0][0] = ffma2(a01.x, b0, acc[0][0]);
            acc[0][1] = ffma2(a01.x, b1, acc[0][1]);
            acc[0][2] = ffma2(a01.x, b2, acc[0][2]);
            acc[0][3] = ffma2(a01.x, b3, acc[0][3]);
            acc[1][0] = ffma2(a01.y, b0, acc[1][0]);
            acc[1][1] = ffma2(a01.y, b1, acc[1][1]);
            acc[1][2] = ffma2(a01.y, b2, acc[1][2]);
            acc[1][3] = ffma2(a01.y, b3, acc[1][3]);
            acc[2][0] = ffma2(a23.x, b0, acc[2][0]);
            acc[2][1] = ffma2(a23.x, b1, acc[2][1]);
            acc[2][2] = ffma2(a23.x, b2, acc[2][2]);
            acc[2][3] = ffma2(a23.x, b3, acc[2][3]);
            acc[3][0] = ffma2(a23.y, b0, acc[3][0]);
            acc[3][1] = ffma2(a23.y, b1, acc[3][1]);
            acc[3][2] = ffma2(a23.y, b2, acc[3][2]);
            acc[3][3] = ffma2(a23.y, b3, acc[3][3]);
        }
    }

    float* base = g_projp + (size_t)blockIdx.y * Bq * Aq + a0 + tx * 4;
#pragma unroll
    for (int mi = 0; mi < 4; ++mi) {
        float4 r0, r1;
        unpack2(acc[mi][0], r0.x, r1.x);
        unpack2(acc[mi][1], r0.y, r1.y);
        unpack2(acc[mi][2], r0.z, r1.z);
        unpack2(acc[mi][3], r0.w, r1.w);
        const int m = ty * 8 + 2 * mi;
        *(float4*)(base + (size_t)m * Aq)       = r0;
        *(float4*)(base + (size_t)(m + 1) * Aq) = r1;
    }
}

// ---------------------------------------------------------------------------
// K2: g_proj = sum_z partials + bias.  Grid 128 x 256 thr, float4/thread.
// ---------------------------------------------------------------------------
__global__ void __launch_bounds__(256) k_reduce(const float* __restrict__ bsa) {
    const int idx = (blockIdx.x * 256 + threadIdx.x) * 4;
    const int a   = idx & (Aq - 1);
    float4 s = *(const float4*)(bsa + a);
#pragma unroll
    for (int z = 0; z < KSPLIT; ++z) {
        float4 p = *(const float4*)(g_projp + (size_t)z * Bq * Aq + idx);
        s.x += p.x;  s.y += p.y;  s.z += p.z;  s.w += p.w;
    }
    *(float4*)(g_proj + idx) = s;
}

// ---------------------------------------------------------------------------
// K3: e~[b,l] = exp(b_a1 + sum_a w_a1[a]*tanh(proj[b,a]+uh[l,b,a])) * mask
// Warp per (l,b); 8 warps share one b. Softmax numerator fused in epilogue.
// Grid: B * L/8 = 2048 blocks, 256 threads.
// ---------------------------------------------------------------------------
__global__ void __launch_bounds__(256) k_scores(const float* __restrict__ uh,
                                                const float* __restrict__ w1,
                                                const float* __restrict__ mask,
                                                const float* __restrict__ ba1) {
    const int b  = blockIdx.x >> 4;
    const int l0 = (blockIdx.x & 15) << 3;
    __shared__ float ps[Aq];
    __shared__ float ws[Aq];
    const int t  = threadIdx.x;
    const int i4 = t * 4;

    *(float4*)&ps[i4] = *(const float4*)(g_proj + (size_t)b * Aq + i4);
    *(float4*)&ws[i4] = *(const float4*)(w1 + i4);
    __syncthreads();

    const int w    = t >> 5;
    const int lane = t & 31;
    const int l    = l0 + w;
    const float* u = uh + (size_t)(l * Bq + b) * Aq;

    float acc = 0.f;
#pragma unroll
    for (int i = 0; i < 8; ++i) {
        int idx = i * 128 + lane * 4;
        float4 u4 = __ldcs((const float4*)(u + idx));
        float4 p4 = *(const float4*)&ps[idx];
        float4 w4 = *(const float4*)&ws[idx];
        acc = fmaf(w4.x, tanh_fast(p4.x + u4.x), acc);
        acc = fmaf(w4.y, tanh_fast(p4.y + u4.y), acc);
        acc = fmaf(w4.z, tanh_fast(p4.z + u4.z), acc);
        acc = fmaf(w4.w, tanh_fast(p4.w + u4.w), acc);
    }
#pragma unroll
    for (int off = 16; off; off >>= 1)
        acc += __shfl_xor_sync(0xffffffffu, acc, off);
    if (lane == 0)
        g_eT[b * Lq + l] = __expf(acc + ba1[0]) * mask[l * Bq + b];
}

// ---------------------------------------------------------------------------
// K4: attend[b,h] = (1/S_b) * sum_l e~[l,b] * xs_h[l,b,h];  S_b = sum_l e~.
// Block = (b, 256-wide h chunk), 256 threads = 64 cols(x4) * 4 l-groups.
// Prologue: coalesced e~ load + in-block sum (cheap). h0==0 writes e_ij.
// 4-way load batching (MLP_p1=4), evict-first streaming. Grid: B*8 = 1024.
// ---------------------------------------------------------------------------
__global__ void __launch_bounds__(256) k_attend(const float* __restrict__ xs,
                                                float* __restrict__ e_out,
                                                float* __restrict__ out) {
    const int b  = blockIdx.x >> 3;
    const int h0 = (blockIdx.x & 7) * 256;
    const int t  = threadIdx.x;

    __shared__ float  es[Lq];
    __shared__ float  red[4];
    __shared__ float4 pacc[256];

    float ev = 0.f;
    if (t < 128) ev = g_eT[b * Lq + t];
    float v = ev;
#pragma unroll
    for (int off = 16; off; off >>= 1)
        v += __shfl_xor_sync(0xffffffffu, v, off);
    if (t < 128) {
        if ((t & 31) == 0) red[t >> 5] = v;
        es[t] = ev;
    }
    __syncthreads();
    const float inv = 1.f / ((red[0] + red[1]) + (red[2] + red[3]));
    if (h0 == 0 && t < 128) e_out[t * Bq + b] = es[t] * inv;

    const int col = t & 63;
    const int g   = t >> 6;
    const float* base = xs + (size_t)(g * 32) * Bq * Hq +
                        (size_t)b * Hq + h0 + col * 4;
    float4 a0 = make_float4(0.f, 0.f, 0.f, 0.f);
    float4 a1 = make_float4(0.f, 0.f, 0.f, 0.f);
    float4 a2 = make_float4(0.f, 0.f, 0.f, 0.f);
    float4 a3 = make_float4(0.f, 0.f, 0.f, 0.f);
#pragma unroll
    for (int i = 0; i < 32; i += 4) {
        float4 v0 = __ldcs((const float4*)(base + (size_t)(i + 0) * Bq * Hq));
        float4 v1 = __ldcs((const float4*)(base + (size_t)(i + 1) * Bq * Hq));
        float4 v2 = __ldcs((const float4*)(base + (size_t)(i + 2) * Bq * Hq));
        float4 v3 = __ldcs((const float4*)(base + (size_t)(i + 3) * Bq * Hq));
        float e0 = es[g * 32 + i + 0];
        float e1 = es[g * 32 + i + 1];
        float e2 = es[g * 32 + i + 2];
        float e3 = es[g * 32 + i + 3];
        a0.x = fmaf(e0, v0.x, a0.x);  a0.y = fmaf(e0, v0.y, a0.y);
        a0.z = fmaf(e0, v0.z, a0.z);  a0.w = fmaf(e0, v0.w, a0.w);
        a1.x = fmaf(e1, v1.x, a1.x);  a1.y = fmaf(e1, v1.y, a1.y);
        a1.z = fmaf(e1, v1.z, a1.z);  a1.w = fmaf(e1, v1.w, a1.w);
        a2.x = fmaf(e2, v2.x, a2.x);  a2.y = fmaf(e2, v2.y, a2.y);
        a2.z = fmaf(e2, v2.z, a2.z);  a2.w = fmaf(e2, v2.w, a2.w);
        a3.x = fmaf(e3, v3.x, a3.x);  a3.y = fmaf(e3, v3.y, a3.y);
        a3.z = fmaf(e3, v3.z, a3.z);  a3.w = fmaf(e3, v3.w, a3.w);
    }
    a0.x = (a0.x + a1.x) + (a2.x + a3.x);
    a0.y = (a0.y + a1.y) + (a2.y + a3.y);
    a0.z = (a0.z + a1.z) + (a2.z + a3.z);
    a0.w = (a0.w + a1.w) + (a2.w + a3.w);
    pacc[t] = a0;
    __syncthreads();
    if (g == 0) {
        float4 p1 = pacc[col + 64];
        float4 p2 = pacc[col + 128];
        float4 p3 = pacc[col + 192];
        a0.x = ((a0.x + p1.x) + (p2.x + p3.x)) * inv;
        a0.y = ((a0.y + p1.y) + (p2.y + p3.y)) * inv;
        a0.z = ((a0.z + p1.z) + (p2.z + p3.z)) * inv;
        a0.w = ((a0.w + p1.w) + (p2.w + p3.w)) * inv;
        *(float4*)(out + (size_t)b * Hq + h0 + col * 4) = a0;
    }
}

// ---------------------------------------------------------------------------
extern "C" void kernel_launch(void* const* d_in, const int* in_sizes, int n_in,
                              void* d_out, int out_size) {
    const float* s_tm1 = (const float*)d_in[0];
    const float* xs_h  = (const float*)d_in[1];
    const float* uh    = (const float*)d_in[2];
    const float* mask  = (const float*)d_in[3];
    const float* W_sa  = (const float*)d_in[4];
    const float* b_sa  = (const float*)d_in[5];
    const float* w_a1  = (const float*)d_in[6];
    const float* b_a1  = (const float*)d_in[7];
    float* out = (float*)d_out;  // [0 : L*B) = e_ij, [L*B : ) = attend

    k_proj<<<dim3(16, KSPLIT), 256>>>(s_tm1, W_sa);
    k_reduce<<<128, 256>>>(b_sa);
    k_scores<<<2048, 256>>>(uh, w_a1, mask, b_a1);
    k_attend<<<1024, 256>>>(xs_h, out, out + Lq * Bq);
}

// round 7
// speedup vs baseline: 1.0429x; 1.0087x over previous
#include <cuda_runtime.h>

#define Lq 128
#define Bq 128
#define Dq 1024
#define Aq 1024
#define Hq 2048
#define KSPLIT 16
#define KC (Dq / KSPLIT)   // 64 k per split block

typedef unsigned long long ull;

// Scratch (device globals: allocation-free, graph-safe)
__device__ float g_projp[KSPLIT * Bq * Aq];  // split-K partials (8MB, L2-resident)
__device__ float g_proj[Bq * Aq];            // reduced proj + bias
__device__ float g_eT[Bq * Lq];              // UNNORMALIZED e~ = exp(score+b)*mask, (B,L)

__device__ __forceinline__ float tanh_fast(float x) {
    float y;
    asm("tanh.approx.f32 %0, %1;" : "=f"(y) : "f"(x));
    return y;
}
__device__ __forceinline__ ull pack2(float x, float y) {
    ull r;
    asm("mov.b64 %0, {%1, %2};" : "=l"(r) : "f"(x), "f"(y));
    return r;
}
__device__ __forceinline__ void unpack2(ull v, float& lo, float& hi) {
    asm("mov.b64 {%0, %1}, %2;" : "=f"(lo), "=f"(hi) : "l"(v));
}
__device__ __forceinline__ ull ffma2(ull a, ull b, ull c) {
    ull d;
    asm("fma.rn.f32x2 %0, %1, %2, %3;" : "=l"(d) : "l"(a), "l"(b), "l"(c));
    return d;
}

// ---------------------------------------------------------------------------
// K1: proj partials. Register-tiled f32x2 SGEMM: 128(b) x 64(a), KT=16,
// split-K=16. Grid (16, 16) = 256 blocks -> 2 blocks/SM (16 warps/SM) so
// the second block's FFMA covers the first block's LDS latency + syncs.
// 256 threads; 8(m) x 4(n) register tile per thread as f32x2 pairs.
// ---------------------------------------------------------------------------
__global__ void __launch_bounds__(256) k_proj(const float* __restrict__ S,
                                              const float* __restrict__ W) {
    const int a0    = blockIdx.x * 64;
    const int kbase = blockIdx.y * KC;

    __shared__ float As[16][132];  // [k][m]
    __shared__ float Bs[16][68];   // [k][n]

    const int t  = threadIdx.x;
    const int ar = t >> 1;
    const int ac = (t & 1) * 8;
    const int br = t >> 2;
    const int bc = (t & 3) * 4;
    const int tx = t & 15;
    const int ty = t >> 4;

    ull acc[4][4];
#pragma unroll
    for (int i = 0; i < 4; ++i)
#pragma unroll
        for (int j = 0; j < 4; ++j) acc[i][j] = 0ull;

    for (int kt = 0; kt < KC; kt += 16) {
        const int k0 = kbase + kt;
        float4 av0 = *(const float4*)(S + (size_t)ar * Dq + k0 + ac);
        float4 av1 = *(const float4*)(S + (size_t)ar * Dq + k0 + ac + 4);
        float4 bv  = *(const float4*)(W + (size_t)(a0 + br) * Dq + k0 + bc);
        __syncthreads();
        As[ac + 0][ar] = av0.x;  As[ac + 1][ar] = av0.y;
        As[ac + 2][ar] = av0.z;  As[ac + 3][ar] = av0.w;
        As[ac + 4][ar] = av1.x;  As[ac + 5][ar] = av1.y;
        As[ac + 6][ar] = av1.z;  As[ac + 7][ar] = av1.w;
        Bs[bc + 0][br] = bv.x;   Bs[bc + 1][br] = bv.y;
        Bs[bc + 2][br] = bv.z;   Bs[bc + 3][br] = bv.w;
        __syncthreads();
#pragma unroll
        for (int kk = 0; kk < 16; ++kk) {
            ulonglong2 a01 = *(const ulonglong2*)&As[kk][ty * 8];
            ulonglong2 a23 = *(const ulonglong2*)&As[kk][ty * 8 + 4];
            float4 b = *(const float4*)&Bs[kk][tx * 4];
            ull b0 = pack2(b.x, b.x), b1 = pack2(b.y, b.y);
            ull b2 = pack2(b.z, b.z), b3 = pack2(b.w, b.w);
            acc[0][0] = ffma2(a01.x, b0, acc[0][0]);
            acc[0][1] = ffma2(a01.x, b1, acc[0][1]);
            acc[0][2] = ffma2(a01.x, b2, acc[0][2]);
            acc[0][3] = ffma2(a01.x, b3, acc[0][3]);
            acc[1][0] = ffma2(a01.y, b0, acc[1][0]);
            acc[1][1] = ffma2(a01.y, b1, acc[1][1]);
            acc[1][2] = ffma2(a01.y, b2, acc[1][2]);
            acc[1][3] = ffma2(a01.y, b3, acc[1][3]);
            acc[2][0] = ffma2(a23.x, b0, acc[2][0]);
            acc[2][1] = ffma2(a23.x, b1, acc[2][1]);
            acc[2][2] = ffma2(a23.x, b2, acc[2][2]);
            acc[2][3] = ffma2(a23.x, b3, acc[2][3]);
            acc[3][0] = ffma2(a23.y, b0, acc[3][0]);
            acc[3][1] = ffma2(a23.y, b1, acc[3][1]);
            acc[3][2] = ffma2(a23.y, b2, acc[3][2]);
            acc[3][3] = ffma2(a23.y, b3, acc[3][3]);
        }
    }

    float* base = g_projp + (size_t)blockIdx.y * Bq * Aq + a0 + tx * 4;
#pragma unroll
    for (int mi = 0; mi < 4; ++mi) {
        float4 r0, r1;
        unpack2(acc[mi][0], r0.x, r1.x);
        unpack2(acc[mi][1], r0.y, r1.y);
        unpack2(acc[mi][2], r0.z, r1.z);
        unpack2(acc[mi][3], r0.w, r1.w);
        const int m = ty * 8 + 2 * mi;
        *(float4*)(base + (size_t)m * Aq)       = r0;
        *(float4*)(base + (size_t)(m + 1) * Aq) = r1;
    }
}

// ---------------------------------------------------------------------------
// K2: g_proj = sum_z partials + bias.  Grid 128 x 256 thr, float4/thread.
// Partials are L2-resident (8MB).
// ---------------------------------------------------------------------------
__global__ void __launch_bounds__(256) k_reduce(const float* __restrict__ bsa) {
    const int idx = (blockIdx.x * 256 + threadIdx.x) * 4;
    const int a   = idx & (Aq - 1);
    float4 s = *(const float4*)(bsa + a);
#pragma unroll
    for (int z = 0; z < KSPLIT; ++z) {
        float4 p = *(const float4*)(g_projp + (size_t)z * Bq * Aq + idx);
        s.x += p.x;  s.y += p.y;  s.z += p.z;  s.w += p.w;
    }
    *(float4*)(g_proj + idx) = s;
}

// ---------------------------------------------------------------------------
// K3: e~[b,l] = exp(b_a1 + sum_a w_a1[a]*tanh(proj[b,a]+uh[l,b,a])) * mask
// Warp per (l,b); 8 warps share one b. Softmax numerator fused in epilogue.
// Grid: B * L/8 = 2048 blocks, 256 threads.
// ---------------------------------------------------------------------------
__global__ void __launch_bounds__(256) k_scores(const float* __restrict__ uh,
                                                const float* __restrict__ w1,
                                                const float* __restrict__ mask,
                                                const float* __restrict__ ba1) {
    const int b  = blockIdx.x >> 4;
    const int l0 = (blockIdx.x & 15) << 3;
    __shared__ float ps[Aq];
    __shared__ float ws[Aq];
    const int t  = threadIdx.x;
    const int i4 = t * 4;

    *(float4*)&ps[i4] = *(const float4*)(g_proj + (size_t)b * Aq + i4);
    *(float4*)&ws[i4] = *(const float4*)(w1 + i4);
    __syncthreads();

    const int w    = t >> 5;
    const int lane = t & 31;
    const int l    = l0 + w;
    const float* u = uh + (size_t)(l * Bq + b) * Aq;

    float acc = 0.f;
#pragma unroll
    for (int i = 0; i < 8; ++i) {
        int idx = i * 128 + lane * 4;
        float4 u4 = __ldcs((const float4*)(u + idx));
        float4 p4 = *(const float4*)&ps[idx];
        float4 w4 = *(const float4*)&ws[idx];
        acc = fmaf(w4.x, tanh_fast(p4.x + u4.x), acc);
        acc = fmaf(w4.y, tanh_fast(p4.y + u4.y), acc);
        acc = fmaf(w4.z, tanh_fast(p4.z + u4.z), acc);
        acc = fmaf(w4.w, tanh_fast(p4.w + u4.w), acc);
    }
#pragma unroll
    for (int off = 16; off; off >>= 1)
        acc += __shfl_xor_sync(0xffffffffu, acc, off);
    if (lane == 0)
        g_eT[b * Lq + l] = __expf(acc + ba1[0]) * mask[l * Bq + b];
}

// ---------------------------------------------------------------------------
// K4: attend[b,h] = (1/S_b) * sum_l e~[l,b] * xs_h[l,b,h];  S_b = sum_l e~.
// Block = (b, 256-wide h chunk), 256 threads = 64 cols(x4) * 4 l-groups.
// h0==0 blocks also write normalized e_ij. Grid: B*8 = 1024 blocks.
// ---------------------------------------------------------------------------
__global__ void __launch_bounds__(256) k_attend(const float* __restrict__ xs,
                                                float* __restrict__ e_out,
                                                float* __restrict__ out) {
    const int b  = blockIdx.x >> 3;
    const int h0 = (blockIdx.x & 7) * 256;
    const int t  = threadIdx.x;

    __shared__ float  es[Lq];
    __shared__ float  red[4];
    __shared__ float4 pacc[256];

    float ev = 0.f;
    if (t < 128) ev = g_eT[b * Lq + t];
    float v = ev;
#pragma unroll
    for (int off = 16; off; off >>= 1)
        v += __shfl_xor_sync(0xffffffffu, v, off);
    if (t < 128) {
        if ((t & 31) == 0) red[t >> 5] = v;
        es[t] = ev;
    }
    __syncthreads();
    const float inv = 1.f / ((red[0] + red[1]) + (red[2] + red[3]));
    if (h0 == 0 && t < 128) e_out[t * Bq + b] = es[t] * inv;

    const int col = t & 63;
    const int g   = t >> 6;
    const float* base = xs + (size_t)(g * 32) * Bq * Hq +
                        (size_t)b * Hq + h0 + col * 4;
    float4 a0 = make_float4(0.f, 0.f, 0.f, 0.f);
    float4 a1 = make_float4(0.f, 0.f, 0.f, 0.f);
#pragma unroll
    for (int i = 0; i < 32; i += 2) {
        float4 v0 = __ldcs((const float4*)(base + (size_t)(i + 0) * Bq * Hq));
        float4 v1 = __ldcs((const float4*)(base + (size_t)(i + 1) * Bq * Hq));
        float e0 = es[g * 32 + i + 0];
        float e1 = es[g * 32 + i + 1];
        a0.x = fmaf(e0, v0.x, a0.x);  a0.y = fmaf(e0, v0.y, a0.y);
        a0.z = fmaf(e0, v0.z, a0.z);  a0.w = fmaf(e0, v0.w, a0.w);
        a1.x = fmaf(e1, v1.x, a1.x);  a1.y = fmaf(e1, v1.y, a1.y);
        a1.z = fmaf(e1, v1.z, a1.z);  a1.w = fmaf(e1, v1.w, a1.w);
    }
    a0.x += a1.x;  a0.y += a1.y;  a0.z += a1.z;  a0.w += a1.w;
    pacc[t] = a0;
    __syncthreads();
    if (g == 0) {
        float4 p1 = pacc[col + 64];
        float4 p2 = pacc[col + 128];
        float4 p3 = pacc[col + 192];
        a0.x = ((a0.x + p1.x) + (p2.x + p3.x)) * inv;
        a0.y = ((a0.y + p1.y) + (p2.y + p3.y)) * inv;
        a0.z = ((a0.z + p1.z) + (p2.z + p3.z)) * inv;
        a0.w = ((a0.w + p1.w) + (p2.w + p3.w)) * inv;
        *(float4*)(out + (size_t)b * Hq + h0 + col * 4) = a0;
    }
}

// ---------------------------------------------------------------------------
extern "C" void kernel_launch(void* const* d_in, const int* in_sizes, int n_in,
                              void* d_out, int out_size) {
    const float* s_tm1 = (const float*)d_in[0];
    const float* xs_h  = (const float*)d_in[1];
    const float* uh    = (const float*)d_in[2];
    const float* mask  = (const float*)d_in[3];
    const float* W_sa  = (const float*)d_in[4];
    const float* b_sa  = (const float*)d_in[5];
    const float* w_a1  = (const float*)d_in[6];
    const float* b_a1  = (const float*)d_in[7];
    float* out = (float*)d_out;  // [0 : L*B) = e_ij, [L*B : ) = attend

    k_proj<<<dim3(16, KSPLIT), 256>>>(s_tm1, W_sa);
    k_reduce<<<128, 256>>>(b_sa);
    k_scores<<<2048, 256>>>(uh, w_a1, mask, b_a1);
    k_attend<<<1024, 256>>>(xs_h, out, out + Lq * Bq);
}